// round 16
// baseline (speedup 1.0000x reference)
#include <cuda_runtime.h>
#include <cuda_fp16.h>
#include <cstdint>

// ============================================================================
// out[z,k] = sum_{i,j} M[k,i,j] * f1[z,i] * f2[z,j]
// SPARSE fp16 warp-MMA GEMM (2:4 structured, fp32 accum):
//   out^T[k,z] = A[k,K] @ B[K,z],  K = i*32+j (i-major),
//   A = M flattened [64 x 1024], ~8% dense -> 2:4 compressible (99.8% of
//   groups); violating groups keep top-2 |v|, dropped entries corrected
//   exactly in the epilogue from a violator list.
//   B[K,z] = f1[z,i]*f2[z,j], generated in registers (HMUL2).
// mma.sp::ordered_metadata.m16n8k32: 2x K-work per instruction vs R8's
// dense k16 -> MMA instr count 4.19M -> 2.10M.
// ============================================================================

#define N_I 32
#define N_J 32
#define N_K 64
#define Z_CTA 128
#define NTHREADS 256
#define N_CH 32                // K-chunks of 32 (one i each)
#define VCAP 4096

// Packed sparse A: [chunk][mt(4)][lane(32)] uint4 {a0,a1,a2,a3}
//   a0: row k0=mt*16+gr, ccols {2q,2q+1}; a1: row k1=k0+8 same ccols;
//   a2: row k0 ccols {2q+8,2q+9};        a3: row k1 same.   (gr=lane/4,q=lane%4)
//   ccol 2g/2g+1 = the 2 kept values of dense group g (dense j = 4g+idx).
__device__ uint4 g_A[N_CH * 4 * 32];                   // 64 KB
// Metadata: [chunk][kt(2)][lane(32)] uint2 {e(mt=2kt), e(mt=2kt+1)}
//   e (thread Tq, qq=q&1): covers groups qq*4..qq*4+3 (dense k half),
//   bits[0:16) row k0 (4 groups x 4b, ascending g), bits[16:32) row k1.
//   4-bit group = idx0 | idx1<<2 (ascending indices).
__device__ uint2 g_E[N_CH * 2 * 32];                   // 16 KB
// Violator list (entries dropped from >2-dense groups)
__device__ int   g_vcount;
__device__ int   g_vidx[VCAP];                         // (k<<10)|(i<<5)|j
__device__ float g_vval[VCAP];

// ---------------------------------------------------------------------------
__global__ void etp_reset_kernel() {
    if (threadIdx.x == 0) g_vcount = 0;
}

__global__ void etp_pack_sp_kernel(const float* __restrict__ Mx) {
    int t = blockIdx.x * blockDim.x + threadIdx.x;     // 0..4095
    if (t >= N_CH * 128) return;
    int i    = t >> 7;
    int rem  = t & 127;
    int mt   = rem >> 5;
    int lane = rem & 31;
    int gr   = lane >> 2;
    int q    = lane & 3;
    int krow[2] = { mt * 16 + gr, mt * 16 + gr + 8 };

    float    cv[2][16];
    uint32_t m16[2][2];
    for (int r = 0; r < 2; r++) {
        const float* row = Mx + (size_t)krow[r] * 1024 + i * 32;
        uint32_t mlo = 0, mhi = 0;
        for (int g = 0; g < 8; g++) {
            float x[4];
            for (int jj = 0; jj < 4; jj++) x[jj] = row[4 * g + jj];
            // top-2 by (nonzero, |v|), ties -> lower index
            float b0v = -2.f, b1v = -2.f; int i0 = 0, i1 = 1;
            for (int jj = 0; jj < 4; jj++) {
                float a = (x[jj] != 0.f) ? fabsf(x[jj]) : -1.f;
                if (a > b0v)      { i1 = i0; b1v = b0v; i0 = jj; b0v = a; }
                else if (a > b1v) { i1 = jj; b1v = a; }
            }
            int idx0 = min(i0, i1), idx1 = max(i0, i1);
            cv[r][2 * g]     = x[idx0];
            cv[r][2 * g + 1] = x[idx1];
            uint32_t m4 = (uint32_t)idx0 | ((uint32_t)idx1 << 2);
            if (g < 4) mlo |= m4 << (4 * g); else mhi |= m4 << (4 * (g - 4));
            if (q == 0) {                              // unique per (i,mt,gr)
                for (int jj = 0; jj < 4; jj++)
                    if (x[jj] != 0.f && jj != idx0 && jj != idx1) {
                        int slot = atomicAdd(&g_vcount, 1);
                        if (slot < VCAP) {
                            g_vidx[slot] = (krow[r] << 10) | (i << 5) | (4 * g + jj);
                            g_vval[slot] = x[jj];
                        }
                    }
            }
        }
        m16[r][0] = mlo; m16[r][1] = mhi;
    }

    __half2 h;
    uint4 A;
    h = __floats2half2_rn(cv[0][2 * q],     cv[0][2 * q + 1]); A.x = *(uint32_t*)&h;
    h = __floats2half2_rn(cv[1][2 * q],     cv[1][2 * q + 1]); A.y = *(uint32_t*)&h;
    h = __floats2half2_rn(cv[0][2 * q + 8], cv[0][2 * q + 9]); A.z = *(uint32_t*)&h;
    h = __floats2half2_rn(cv[1][2 * q + 8], cv[1][2 * q + 9]); A.w = *(uint32_t*)&h;
    g_A[(i * 4 + mt) * 32 + lane] = A;

    uint32_t e = m16[0][q & 1] | (m16[1][q & 1] << 16);
    uint32_t* pe = reinterpret_cast<uint32_t*>(&g_E[(i * 2 + (mt >> 1)) * 32 + lane]);
    pe[mt & 1] = e;
}

// ---------------------------------------------------------------------------

#define HMUL2(d, x, y) \
    asm("mul.rn.f16x2 %0, %1, %2;" : "=r"(d) : "r"(x), "r"(y))

#define MMA_SP(cacc, Ar, b0, b1, b2, b3, e)                                   \
    asm volatile(                                                             \
        "mma.sp::ordered_metadata.sync.aligned.m16n8k32.row.col.f32.f16.f16.f32 " \
        "{%0,%1,%2,%3}, {%4,%5,%6,%7}, {%8,%9,%10,%11}, {%0,%1,%2,%3}, %12, 0x0;" \
        : "+f"((cacc)[0]), "+f"((cacc)[1]), "+f"((cacc)[2]), "+f"((cacc)[3])  \
        : "r"((Ar).x), "r"((Ar).y), "r"((Ar).z), "r"((Ar).w),                 \
          "r"(b0), "r"(b1), "r"(b2), "r"(b3), "r"(e))

__global__ void __launch_bounds__(NTHREADS, 2)
etp_mma_sp_kernel(const float* __restrict__ F1,
                  const float* __restrict__ F2,
                  float* __restrict__ Out) {
    // f1 broadcast half2(v,v): word = row*32 + (i ^ ((row&7)<<2))
    __shared__ uint32_t f1h[Z_CTA * 32];               // 16 KB

    const int tid  = threadIdx.x;
    const int warp = tid >> 5;
    const int lane = tid & 31;
    const int zs   = warp & 3;           // z-subtile 0..3 (32 z each)
    const int kt   = warp >> 2;          // k-half 0..1 (mtiles 2kt, 2kt+1)
    const int gr   = lane >> 2;          // 0..7
    const int q    = lane & 3;           // 0..3

    const size_t zbase = (size_t)blockIdx.x * Z_CTA;
    const int zw = zs * 32;              // warp z offset (local)

    // ---- stage f1 (broadcast half2, swizzled) ----
    {
        const float4* f1g = reinterpret_cast<const float4*>(F1 + zbase * N_I);
#pragma unroll
        for (int t = 0; t < 4; t++) {
            int i4 = tid + t * NTHREADS;          // 0..1023
            int row = i4 >> 3, cg = i4 & 7;
            float4 v1 = __ldg(f1g + i4);
            __half2 h0 = __half2half2(__float2half_rn(v1.x));
            __half2 h1 = __half2half2(__float2half_rn(v1.y));
            __half2 h2 = __half2half2(__float2half_rn(v1.z));
            __half2 h3 = __half2half2(__float2half_rn(v1.w));
            uint4 pk;
            pk.x = *reinterpret_cast<uint32_t*>(&h0);
            pk.y = *reinterpret_cast<uint32_t*>(&h1);
            pk.z = *reinterpret_cast<uint32_t*>(&h2);
            pk.w = *reinterpret_cast<uint32_t*>(&h3);
            int col = (cg * 4) ^ ((row & 7) << 2);
            *reinterpret_cast<uint4*>(&f1h[row * 32 + col]) = pk;
        }
    }

    // ---- f2 pairs (B operand needs z = zw + nt*8 + gr, pairs {q+4m}) ----
    uint32_t f2h[4][4];
#pragma unroll
    for (int nt = 0; nt < 4; nt++) {
        const float* fr = F2 + (zbase + zw + nt * 8 + gr) * N_J;
#pragma unroll
        for (int m = 0; m < 4; m++) {
            float2 v = *reinterpret_cast<const float2*>(fr + 2 * (q + 4 * m));
            __half2 h = __floats2half2_rn(v.x, v.y);
            f2h[nt][m] = *reinterpret_cast<uint32_t*>(&h);
        }
    }

    float C[2][4][4];                    // [mtile][ntile][quad]
#pragma unroll
    for (int m = 0; m < 2; m++)
#pragma unroll
        for (int nt = 0; nt < 4; nt++)
#pragma unroll
            for (int qq = 0; qq < 4; qq++) C[m][nt][qq] = 0.0f;

    __syncthreads();

    const uint4* pA = g_A + (kt * 2) * 32 + lane;      // stride 128/chunk
    const uint2* pE = g_E + kt * 32 + lane;            // stride 64/chunk

#pragma unroll 2
    for (int i = 0; i < N_CH; i++) {
        const uint4 A0 = pA[0];
        const uint4 A1 = pA[32];
        const uint2 E  = pE[0];
        pA += 128;
        pE += 64;

        const int icol = i ^ (gr << 2);
#pragma unroll
        for (int nt = 0; nt < 4; nt++) {
            const uint32_t f1b = f1h[(zw + nt * 8 + gr) * 32 + icol];
            uint32_t b0, b1, b2, b3;
            HMUL2(b0, f1b, f2h[nt][0]);
            HMUL2(b1, f1b, f2h[nt][1]);
            HMUL2(b2, f1b, f2h[nt][2]);
            HMUL2(b3, f1b, f2h[nt][3]);
            MMA_SP(C[0][nt], A0, b0, b1, b2, b3, E.x);
            MMA_SP(C[1][nt], A1, b0, b1, b2, b3, E.y);
        }
    }

    // ---- exact fixup for 2:4-violating dropped entries ----
    {
        int vc = g_vcount;
        if (vc > VCAP) vc = VCAP;
        const int ktbase = kt * 32;
        for (int v = 0; v < vc; v++) {
            const int pk = g_vidx[v];
            const int kv = pk >> 10, iv = (pk >> 5) & 31, jv = pk & 31;
            const int rel = kv - ktbase;
            if ((unsigned)rel >= 32u) continue;
            const int m = rel >> 4;
            const int rr = rel & 15;
            if ((rr & 7) != gr) continue;
            const int half = rr >> 3;            // 0 -> c0/c1, 1 -> c2/c3
            const float val = g_vval[v];
#pragma unroll
            for (int nt = 0; nt < 4; nt++) {
                const size_t z0 = zbase + zw + nt * 8 + 2 * q;
                C[m][nt][half * 2 + 0] += val * F1[z0 * N_I + iv] * F2[z0 * N_J + jv];
                C[m][nt][half * 2 + 1] += val * F1[(z0 + 1) * N_I + iv] * F2[(z0 + 1) * N_J + jv];
            }
        }
    }

    // ---- epilogue: C cols = z (2q, 2q+1), rows = k (gr, gr+8) ----
#pragma unroll
    for (int m = 0; m < 2; m++) {
        const int kb = (kt * 2 + m) * 16 + gr;
#pragma unroll
        for (int nt = 0; nt < 4; nt++) {
            const size_t z0 = zbase + zw + nt * 8 + 2 * q;
            Out[z0 * N_K + kb]           = C[m][nt][0];
            Out[(z0 + 1) * N_K + kb]     = C[m][nt][1];
            Out[z0 * N_K + kb + 8]       = C[m][nt][2];
            Out[(z0 + 1) * N_K + kb + 8] = C[m][nt][3];
        }
    }
}

// ---------------------------------------------------------------------------

extern "C" void kernel_launch(void* const* d_in, const int* in_sizes, int n_in,
                              void* d_out, int out_size) {
    const float* f1 = (const float*)d_in[0];   // [Z, 32]
    const float* f2 = (const float*)d_in[1];   // [Z, 32]
    const float* mx = (const float*)d_in[2];   // [64, 32, 32]
    float* out = (float*)d_out;                // [Z, 64]

    const int z_total = in_sizes[0] / N_I;     // 131072
    const int blocks = z_total / Z_CTA;        // 1024

    etp_reset_kernel<<<1, 32>>>();
    etp_pack_sp_kernel<<<16, 256>>>(mx);       // 4096 threads
    etp_mma_sp_kernel<<<blocks, NTHREADS>>>(f1, f2, out);
}

// round 17
// speedup vs baseline: 1.1244x; 1.1244x over previous
#include <cuda_runtime.h>
#include <cuda_fp16.h>
#include <cstdint>

// ============================================================================
// out[z,k] = sum_{i,j} M[k,i,j] * f1[z,i] * f2[z,j]
// SPARSE fp16 warp-MMA GEMM (2:4 structured, fp32 accum):
//   out^T[k,z] = A[k,K] @ B[K,z],  K = i*32+j (i-major)
//   A = M flat [64 x 1024] (~8% dense): 2:4 keep-top-2 per j-group, rare
//   violating groups (>2 nnz) corrected EXACTLY via a violator list in the
//   epilogue.  B[K,z] = f1[z,i]*f2[z,j] generated in regs (HMUL2).
// mma.sp::ordered_metadata.m16n8k32 -> 2x K per instruction vs dense k16.
//
// R17 = R16 with the pack kernel slimmed 4x (per-thread owns only its 4
//   groups; metadata gathered via one packed shuffle; float4 loads; 32x128
//   launch). mma_sp kernel unchanged (validated in R16).
// ============================================================================

#define N_I 32
#define N_J 32
#define N_K 64
#define Z_CTA 128
#define NTHREADS 256
#define N_CH 32                // K-chunks of 32 (one i each)
#define VCAP 4096

// Packed sparse A: [chunk][mt(4)][lane(32)] uint4 {a0,a1,a2,a3}
//   a0: row k0=mt*16+gr, group q ; a1: row k1=k0+8, group q ;
//   a2: row k0, group q+4       ; a3: row k1, group q+4.  (gr=lane/4,q=lane%4)
__device__ uint4 g_A[N_CH * 4 * 32];                   // 64 KB
// Metadata: [chunk][kt(2)][lane(32)] uint2 {e(mt=2kt), e(mt=2kt+1)}
//   e (qq=q&1): bits[0:16) row k0 groups qq*4+t at bits 4t; [16:32) row k1.
__device__ uint2 g_E[N_CH * 2 * 32];                   // 16 KB
// Violator list (entries dropped from >2-dense groups)
__device__ int   g_vcount;
__device__ int   g_vidx[VCAP];                         // (k<<10)|(i<<5)|j
__device__ float g_vval[VCAP];

// ---------------------------------------------------------------------------
__global__ void etp_reset_kernel() {
    if (threadIdx.x == 0) g_vcount = 0;
}

// top-2 of a dense 4-group: returns packed idx code, kept values, violators
static __device__ __forceinline__ uint32_t top2_group(
    const float4 v, float& v0, float& v1, int& d0j, float& d0v, int& d1j, float& d1v)
{
    float x[4] = {v.x, v.y, v.z, v.w};
    float b0v = -2.f, b1v = -2.f; int i0 = 0, i1 = 1;
#pragma unroll
    for (int jj = 0; jj < 4; jj++) {
        float a = (x[jj] != 0.f) ? fabsf(x[jj]) : -1.f;
        if (a > b0v)      { i1 = i0; b1v = b0v; i0 = jj; b0v = a; }
        else if (a > b1v) { i1 = jj; b1v = a; }
    }
    int idx0 = min(i0, i1), idx1 = max(i0, i1);
    v0 = x[idx0]; v1 = x[idx1];
    d0j = -1; d1j = -1;
#pragma unroll
    for (int jj = 0; jj < 4; jj++)
        if (x[jj] != 0.f && jj != idx0 && jj != idx1) {
            if (d0j < 0) { d0j = jj; d0v = x[jj]; }
            else         { d1j = jj; d1v = x[jj]; }
        }
    return (uint32_t)idx0 | ((uint32_t)idx1 << 2);
}

__global__ void etp_pack_sp_kernel(const float* __restrict__ Mx) {
    int t = blockIdx.x * blockDim.x + threadIdx.x;     // 0..4095
    if (t >= N_CH * 128) return;
    int i    = t >> 7;
    int rem  = t & 127;
    int mt   = rem >> 5;
    int lane = rem & 31;
    int gr   = lane >> 2;
    int q    = lane & 3;
    int qq   = q & 1;
    int krow[2] = { mt * 16 + gr, mt * 16 + gr + 8 };

    const float4* M4 = reinterpret_cast<const float4*>(Mx);

    // owned groups: gA = q, gB = q+4, rows k0,k1
    float    cvA[2][2], cvB[2][2];
    uint32_t codepack = 0;
#pragma unroll
    for (int r = 0; r < 2; r++) {
        const int rb = krow[r] * 256 + i * 8;
        float d0v = 0.f, d1v = 0.f; int d0j, d1j;
        // group q
        uint32_t cA = top2_group(__ldg(M4 + rb + q),
                                 cvA[r][0], cvA[r][1], d0j, d0v, d1j, d1v);
        if (d0j >= 0) {
            int s = atomicAdd(&g_vcount, 1);
            if (s < VCAP) { g_vidx[s] = (krow[r] << 10) | (i << 5) | (4 * q + d0j); g_vval[s] = d0v; }
        }
        if (d1j >= 0) {
            int s = atomicAdd(&g_vcount, 1);
            if (s < VCAP) { g_vidx[s] = (krow[r] << 10) | (i << 5) | (4 * q + d1j); g_vval[s] = d1v; }
        }
        // group q+4
        uint32_t cB = top2_group(__ldg(M4 + rb + q + 4),
                                 cvB[r][0], cvB[r][1], d0j, d0v, d1j, d1v);
        if (d0j >= 0) {
            int s = atomicAdd(&g_vcount, 1);
            if (s < VCAP) { g_vidx[s] = (krow[r] << 10) | (i << 5) | (4 * (q + 4) + d0j); g_vval[s] = d0v; }
        }
        if (d1j >= 0) {
            int s = atomicAdd(&g_vcount, 1);
            if (s < VCAP) { g_vidx[s] = (krow[r] << 10) | (i << 5) | (4 * (q + 4) + d1j); g_vval[s] = d1v; }
        }
        codepack |= (cA << (8 * r)) | (cB << (8 * r + 4));
    }

    // A fragment
    __half2 h;
    uint4 A;
    h = __floats2half2_rn(cvA[0][0], cvA[0][1]); A.x = *(uint32_t*)&h;
    h = __floats2half2_rn(cvA[1][0], cvA[1][1]); A.y = *(uint32_t*)&h;
    h = __floats2half2_rn(cvB[0][0], cvB[0][1]); A.z = *(uint32_t*)&h;
    h = __floats2half2_rn(cvB[1][0], cvB[1][1]); A.w = *(uint32_t*)&h;
    g_A[(i * 4 + mt) * 32 + lane] = A;

    // metadata: gather quad codes
    // codepack layout: bits[0:4) cA r0, [4:8) cB r0, [8:12) cA r1, [12:16) cB r1
    uint32_t e0 = 0, e1 = 0;                           // rows k0, k1
    const int qb = lane & ~3;
#pragma unroll
    for (int tt = 0; tt < 4; tt++) {
        uint32_t w = __shfl_sync(0xffffffffu, codepack, qb + tt);
        uint32_t c0 = (qq == 0) ? (w & 0xF)        : ((w >> 4) & 0xF);   // row k0
        uint32_t c1 = (qq == 0) ? ((w >> 8) & 0xF) : ((w >> 12) & 0xF);  // row k1
        e0 |= c0 << (4 * tt);
        e1 |= c1 << (4 * tt);
    }
    uint32_t e = e0 | (e1 << 16);
    uint32_t* pe = reinterpret_cast<uint32_t*>(&g_E[(i * 2 + (mt >> 1)) * 32 + lane]);
    pe[mt & 1] = e;
}

// ---------------------------------------------------------------------------

#define HMUL2(d, x, y) \
    asm("mul.rn.f16x2 %0, %1, %2;" : "=r"(d) : "r"(x), "r"(y))

#define MMA_SP(cacc, Ar, b0, b1, b2, b3, e)                                   \
    asm volatile(                                                             \
        "mma.sp::ordered_metadata.sync.aligned.m16n8k32.row.col.f32.f16.f16.f32 " \
        "{%0,%1,%2,%3}, {%4,%5,%6,%7}, {%8,%9,%10,%11}, {%0,%1,%2,%3}, %12, 0x0;" \
        : "+f"((cacc)[0]), "+f"((cacc)[1]), "+f"((cacc)[2]), "+f"((cacc)[3])  \
        : "r"((Ar).x), "r"((Ar).y), "r"((Ar).z), "r"((Ar).w),                 \
          "r"(b0), "r"(b1), "r"(b2), "r"(b3), "r"(e))

__global__ void __launch_bounds__(NTHREADS, 2)
etp_mma_sp_kernel(const float* __restrict__ F1,
                  const float* __restrict__ F2,
                  float* __restrict__ Out) {
    // f1 broadcast half2(v,v): word = row*32 + (i ^ ((row&7)<<2))
    __shared__ uint32_t f1h[Z_CTA * 32];               // 16 KB

    const int tid  = threadIdx.x;
    const int warp = tid >> 5;
    const int lane = tid & 31;
    const int zs   = warp & 3;           // z-subtile 0..3 (32 z each)
    const int kt   = warp >> 2;          // k-half 0..1 (mtiles 2kt, 2kt+1)
    const int gr   = lane >> 2;          // 0..7
    const int q    = lane & 3;           // 0..3

    const size_t zbase = (size_t)blockIdx.x * Z_CTA;
    const int zw = zs * 32;              // warp z offset (local)

    // ---- stage f1 (broadcast half2, swizzled) ----
    {
        const float4* f1g = reinterpret_cast<const float4*>(F1 + zbase * N_I);
#pragma unroll
        for (int t = 0; t < 4; t++) {
            int i4 = tid + t * NTHREADS;          // 0..1023
            int row = i4 >> 3, cg = i4 & 7;
            float4 v1 = __ldg(f1g + i4);
            __half2 h0 = __half2half2(__float2half_rn(v1.x));
            __half2 h1 = __half2half2(__float2half_rn(v1.y));
            __half2 h2 = __half2half2(__float2half_rn(v1.z));
            __half2 h3 = __half2half2(__float2half_rn(v1.w));
            uint4 pk;
            pk.x = *reinterpret_cast<uint32_t*>(&h0);
            pk.y = *reinterpret_cast<uint32_t*>(&h1);
            pk.z = *reinterpret_cast<uint32_t*>(&h2);
            pk.w = *reinterpret_cast<uint32_t*>(&h3);
            int col = (cg * 4) ^ ((row & 7) << 2);
            *reinterpret_cast<uint4*>(&f1h[row * 32 + col]) = pk;
        }
    }

    // ---- f2 pairs (B operand: z = zw + nt*8 + gr, pairs {q+4m}) ----
    uint32_t f2h[4][4];
#pragma unroll
    for (int nt = 0; nt < 4; nt++) {
        const float* fr = F2 + (zbase + zw + nt * 8 + gr) * N_J;
#pragma unroll
        for (int m = 0; m < 4; m++) {
            float2 v = *reinterpret_cast<const float2*>(fr + 2 * (q + 4 * m));
            __half2 h = __floats2half2_rn(v.x, v.y);
            f2h[nt][m] = *reinterpret_cast<uint32_t*>(&h);
        }
    }

    float C[2][4][4];                    // [mtile][ntile][quad]
#pragma unroll
    for (int m = 0; m < 2; m++)
#pragma unroll
        for (int nt = 0; nt < 4; nt++)
#pragma unroll
            for (int qq = 0; qq < 4; qq++) C[m][nt][qq] = 0.0f;

    __syncthreads();

    const uint4* pA = g_A + (kt * 2) * 32 + lane;      // stride 128/chunk
    const uint2* pE = g_E + kt * 32 + lane;            // stride 64/chunk

#pragma unroll 2
    for (int i = 0; i < N_CH; i++) {
        const uint4 A0 = pA[0];
        const uint4 A1 = pA[32];
        const uint2 E  = pE[0];
        pA += 128;
        pE += 64;

        const int icol = i ^ (gr << 2);
#pragma unroll
        for (int nt = 0; nt < 4; nt++) {
            const uint32_t f1b = f1h[(zw + nt * 8 + gr) * 32 + icol];
            uint32_t b0, b1, b2, b3;
            HMUL2(b0, f1b, f2h[nt][0]);
            HMUL2(b1, f1b, f2h[nt][1]);
            HMUL2(b2, f1b, f2h[nt][2]);
            HMUL2(b3, f1b, f2h[nt][3]);
            MMA_SP(C[0][nt], A0, b0, b1, b2, b3, E.x);
            MMA_SP(C[1][nt], A1, b0, b1, b2, b3, E.y);
        }
    }

    // ---- exact fixup for 2:4-violating dropped entries ----
    {
        int vc = g_vcount;
        if (vc > VCAP) vc = VCAP;
        const int ktbase = kt * 32;
        for (int v = 0; v < vc; v++) {
            const int pk = __ldg(&g_vidx[v]);
            const int kv = pk >> 10, iv = (pk >> 5) & 31, jv = pk & 31;
            const int rel = kv - ktbase;
            if ((unsigned)rel >= 32u) continue;
            const int m = rel >> 4;
            const int rr = rel & 15;
            if ((rr & 7) != gr) continue;
            const int half = rr >> 3;            // 0 -> c0/c1, 1 -> c2/c3
            const float val = __ldg(&g_vval[v]);
#pragma unroll
            for (int nt = 0; nt < 4; nt++) {
                const size_t z0 = zbase + zw + nt * 8 + 2 * q;
                C[m][nt][half * 2 + 0] += val * __ldg(F1 + z0 * N_I + iv) * __ldg(F2 + z0 * N_J + jv);
                C[m][nt][half * 2 + 1] += val * __ldg(F1 + (z0 + 1) * N_I + iv) * __ldg(F2 + (z0 + 1) * N_J + jv);
            }
        }
    }

    // ---- epilogue: C cols = z (2q, 2q+1), rows = k (gr, gr+8) ----
#pragma unroll
    for (int m = 0; m < 2; m++) {
        const int kb = (kt * 2 + m) * 16 + gr;
#pragma unroll
        for (int nt = 0; nt < 4; nt++) {
            const size_t z0 = zbase + zw + nt * 8 + 2 * q;
            Out[z0 * N_K + kb]           = C[m][nt][0];
            Out[(z0 + 1) * N_K + kb]     = C[m][nt][1];
            Out[z0 * N_K + kb + 8]       = C[m][nt][2];
            Out[(z0 + 1) * N_K + kb + 8] = C[m][nt][3];
        }
    }
}

// ---------------------------------------------------------------------------

extern "C" void kernel_launch(void* const* d_in, const int* in_sizes, int n_in,
                              void* d_out, int out_size) {
    const float* f1 = (const float*)d_in[0];   // [Z, 32]
    const float* f2 = (const float*)d_in[1];   // [Z, 32]
    const float* mx = (const float*)d_in[2];   // [64, 32, 32]
    float* out = (float*)d_out;                // [Z, 64]

    const int z_total = in_sizes[0] / N_I;     // 131072
    const int blocks = z_total / Z_CTA;        // 1024

    etp_reset_kernel<<<1, 32>>>();
    etp_pack_sp_kernel<<<32, 128>>>(mx);       // 4096 threads, lean
    etp_mma_sp_kernel<<<blocks, NTHREADS>>>(f1, f2, out);
}